// round 7
// baseline (speedup 1.0000x reference)
#include <cuda_runtime.h>
#include <cfloat>

#define NROWS   32768
#define NCTR    512
#define DIM     128
#define TOPK    10

#define BM 128
#define BN 128
#define BK 8
#define NSTAGE (DIM / BK)     // 16
#define NCHUNK (NCTR / BN)    // 4
#define NRB    (NROWS / BM)   // 256 rowblocks
#define GCTA 256

// Scratch (static device globals: allocation-free).
__device__ float g_c2[NCTR];
__device__ float g_x2[NROWS];
__device__ float g_keys[(size_t)NROWS * NCTR];   // 64 MB distance keys
__device__ unsigned g_cnt[NRB];                  // zero-init; reset each replay

// ---------------------------------------------------------------------------
// Kernel 0: x2 and c2, correctly rounded (double accumulation). 1 warp/row.
// ---------------------------------------------------------------------------
__global__ void norms_kernel(const float* __restrict__ x,
                             const float* __restrict__ ctr) {
    int warp = (blockIdx.x * blockDim.x + threadIdx.x) >> 5;
    int lane = threadIdx.x & 31;
    const float* src;
    float* dst;
    if (warp < NROWS) {
        src = x + (size_t)warp * DIM;
        dst = &g_x2[warp];
    } else if (warp < NROWS + NCTR) {
        src = ctr + (size_t)(warp - NROWS) * DIM;
        dst = &g_c2[warp - NROWS];
    } else {
        return;
    }
    float4 v = reinterpret_cast<const float4*>(src)[lane];
    double s = (double)v.x * v.x + (double)v.y * v.y
             + (double)v.z * v.z + (double)v.w * v.w;
    #pragma unroll
    for (int o = 16; o; o >>= 1) s += __shfl_xor_sync(0xffffffffu, s, o);
    if (lane == 0) *dst = (float)s;
}

// ---------------------------------------------------------------------------
// Fused GEMM + last-finisher select.
//
// GEMM (exactness invariant, UNCHANGED from R4/R6): 128x128x128 block,
// 8x8 thread tile, BK=8 double-buffered; dot = ONE sequential ascending-k
// FMA chain per element; epilogue d = sqrt_rn(max(fl(fl(x2-fl(2*dot))+c2),0)).
//
// After writing its key block, each CTA arrives on its rowblock counter;
// the 4th arriver (all 512 keys for these 128 rows now visible) performs
// top-10 select + gather for the whole rowblock, overlapping other CTAs'
// FFMA work. Select comparator: u64 (float_bits<<32 | idx), REDUX argmin —
// identical to R6.
// ---------------------------------------------------------------------------
__global__ void __launch_bounds__(GCTA, 2)
gemm_select_kernel(const float* __restrict__ x,
                   const float* __restrict__ ctr,
                   float* __restrict__ out) {
    __shared__ float as[2][BK][BM];
    __shared__ float bs[2][BK][BN];
    __shared__ bool  isLast;

    const int tid    = threadIdx.x;
    const int rbIdx  = blockIdx.y;
    const int rowBlk = rbIdx * BM;
    const int ctrBlk = blockIdx.x * BN;   // chunk fast-varying: adjacent bids

    const int lr = tid >> 1;          // 0..127
    const int lq = tid & 1;           // 0..1
    const float4* xsrc = reinterpret_cast<const float4*>(x   + (size_t)(rowBlk + lr) * DIM);
    const float4* csrc = reinterpret_cast<const float4*>(ctr + (size_t)(ctrBlk + lr) * DIM);

    const int tx = tid & 15;
    const int ty = tid >> 4;

    float acc[8][8];
    #pragma unroll
    for (int i = 0; i < 8; i++)
        #pragma unroll
        for (int j = 0; j < 8; j++) acc[i][j] = 0.0f;

    float4 av = xsrc[lq];
    float4 bv = csrc[lq];
    as[0][lq * 4 + 0][lr] = av.x; as[0][lq * 4 + 1][lr] = av.y;
    as[0][lq * 4 + 2][lr] = av.z; as[0][lq * 4 + 3][lr] = av.w;
    bs[0][lq * 4 + 0][lr] = bv.x; bs[0][lq * 4 + 1][lr] = bv.y;
    bs[0][lq * 4 + 2][lr] = bv.z; bs[0][lq * 4 + 3][lr] = bv.w;
    __syncthreads();

    for (int s = 0; s < NSTAGE; s++) {
        const int buf = s & 1;
        if (s + 1 < NSTAGE) {
            av = xsrc[(s + 1) * 2 + lq];
            bv = csrc[(s + 1) * 2 + lq];
        }

        #pragma unroll
        for (int k = 0; k < BK; k++) {
            float a[8], b[8];
            *reinterpret_cast<float4*>(&a[0]) = *reinterpret_cast<const float4*>(&as[buf][k][ty * 8]);
            *reinterpret_cast<float4*>(&a[4]) = *reinterpret_cast<const float4*>(&as[buf][k][ty * 8 + 4]);
            *reinterpret_cast<float4*>(&b[0]) = *reinterpret_cast<const float4*>(&bs[buf][k][tx * 8]);
            *reinterpret_cast<float4*>(&b[4]) = *reinterpret_cast<const float4*>(&bs[buf][k][tx * 8 + 4]);
            #pragma unroll
            for (int i = 0; i < 8; i++)
                #pragma unroll
                for (int j = 0; j < 8; j++)
                    acc[i][j] = fmaf(a[i], b[j], acc[i][j]);
        }

        if (s + 1 < NSTAGE) {
            const int nbuf = 1 - buf;
            as[nbuf][lq * 4 + 0][lr] = av.x; as[nbuf][lq * 4 + 1][lr] = av.y;
            as[nbuf][lq * 4 + 2][lr] = av.z; as[nbuf][lq * 4 + 3][lr] = av.w;
            bs[nbuf][lq * 4 + 0][lr] = bv.x; bs[nbuf][lq * 4 + 1][lr] = bv.y;
            bs[nbuf][lq * 4 + 2][lr] = bv.z; bs[nbuf][lq * 4 + 3][lr] = bv.w;
            __syncthreads();
        }
    }

    // epilogue: exact reference rounding -> g_keys
    {
        float x2v[8], c2v[8];
        #pragma unroll
        for (int i = 0; i < 8; i++) x2v[i] = g_x2[rowBlk + ty * 8 + i];
        #pragma unroll
        for (int j = 0; j < 8; j++) c2v[j] = g_c2[ctrBlk + tx * 8 + j];

        #pragma unroll
        for (int i = 0; i < 8; i++) {
            const size_t rowOff = (size_t)(rowBlk + ty * 8 + i) * NCTR + ctrBlk + tx * 8;
            #pragma unroll
            for (int g = 0; g < 2; g++) {
                float4 kv;
                float d2;
                d2 = __fadd_rn(__fsub_rn(x2v[i], __fmul_rn(2.0f, acc[i][g*4+0])), c2v[g*4+0]);
                kv.x = __fsqrt_rn(fmaxf(d2, 0.0f));
                d2 = __fadd_rn(__fsub_rn(x2v[i], __fmul_rn(2.0f, acc[i][g*4+1])), c2v[g*4+1]);
                kv.y = __fsqrt_rn(fmaxf(d2, 0.0f));
                d2 = __fadd_rn(__fsub_rn(x2v[i], __fmul_rn(2.0f, acc[i][g*4+2])), c2v[g*4+2]);
                kv.z = __fsqrt_rn(fmaxf(d2, 0.0f));
                d2 = __fadd_rn(__fsub_rn(x2v[i], __fmul_rn(2.0f, acc[i][g*4+3])), c2v[g*4+3]);
                kv.w = __fsqrt_rn(fmaxf(d2, 0.0f));
                *reinterpret_cast<float4*>(&g_keys[rowOff + g * 4]) = kv;
            }
        }
    }

    // ---- rowblock arrival: last finisher runs select for all 128 rows ----
    __threadfence();                      // order key writes before the arrive
    __syncthreads();                      // all threads' fences done
    if (tid == 0) {
        unsigned old = atomicAdd(&g_cnt[rbIdx], 1);
        isLast = (old == NCHUNK - 1);
        if (isLast) g_cnt[rbIdx] = 0;     // reset for next graph replay
    }
    __syncthreads();
    if (!isLast) return;
    __threadfence();                      // acquire: other CTAs' keys visible

    // ---- select + gather: warp w rows w*16 .. w*16+15 ----
    const int warp = tid >> 5;
    const int lane = tid & 31;
    float4* out4 = reinterpret_cast<float4*>(out);

    for (int rr = 0; rr < 16; rr++) {
        const int row = rowBlk + warp * 16 + rr;
        const float4* krow = reinterpret_cast<const float4*>(g_keys + (size_t)row * NCTR);

        // per-lane sorted top-10 (u64 insertion over 16 candidates)
        unsigned long long b[TOPK];
        #pragma unroll
        for (int j = 0; j < TOPK; j++) b[j] = ~0ull;

        #pragma unroll
        for (int q = 0; q < 4; q++) {
            float4 t = krow[q * 32 + lane];
            float vv[4] = {t.x, t.y, t.z, t.w};
            #pragma unroll
            for (int j4 = 0; j4 < 4; j4++) {
                unsigned long long key =
                    ((unsigned long long)__float_as_uint(vv[j4]) << 32)
                    | (unsigned)(q * 128 + lane * 4 + j4);
                if (key < b[TOPK - 1]) {
                    b[TOPK - 1] = key;
                    #pragma unroll
                    for (int j = TOPK - 1; j > 0; j--) {
                        if (b[j] < b[j - 1]) {
                            unsigned long long t2 = b[j]; b[j] = b[j - 1]; b[j - 1] = t2;
                        }
                    }
                }
            }
        }

        // 10 rounds: REDUX argmin over lane heads; winner pops; fused gather.
        const size_t outRowBase = (size_t)row * TOPK;
        #pragma unroll
        for (int s = 0; s < TOPK; s++) {
            unsigned hv = (unsigned)(b[0] >> 32);
            unsigned hi = (unsigned)(b[0] & 0xffffffffu);
            unsigned m  = __reduce_min_sync(0xffffffffu, hv);
            unsigned ci = (hv == m) ? hi : 0xffffffffu;
            unsigned mi = __reduce_min_sync(0xffffffffu, ci);

            const float4* srcRow = reinterpret_cast<const float4*>(x + (size_t)mi * DIM);
            out4[(outRowBase + s) * (DIM / 4) + lane] = srcRow[lane];

            if (hv == m && hi == mi) {
                #pragma unroll
                for (int j = 0; j < TOPK - 1; j++) b[j] = b[j + 1];
                b[TOPK - 1] = ~0ull;
            }
        }
    }
}

// ---------------------------------------------------------------------------
extern "C" void kernel_launch(void* const* d_in, const int* in_sizes, int n_in,
                              void* d_out, int out_size) {
    const float* x;
    const float* ctr;
    if (in_sizes[0] == NCTR * DIM && n_in >= 2) {
        ctr = (const float*)d_in[0];
        x   = (const float*)d_in[1];
    } else {
        x   = (const float*)d_in[0];
        ctr = (const float*)d_in[1];
    }
    float* out = (float*)d_out;

    int totalWarps = NROWS + NCTR;
    int normBlocks = (totalWarps * 32 + 255) / 256;
    norms_kernel<<<normBlocks, 256>>>(x, ctr);

    dim3 ggrid(NCHUNK, NRB);              // chunks fast-varying (adjacent bids)
    gemm_select_kernel<<<ggrid, GCTA>>>(x, ctr, out);
}